// round 6
// baseline (speedup 1.0000x reference)
#include <cuda_runtime.h>
#include <cuda_fp16.h>
#include <mma.h>
using namespace nvcuda;

#define Bv 8
#define Tv 512
#define Mv 16
#define Dv 128
#define Pv 256
#define Hv 8
#define Ev 32
#define ROWS (Bv*Tv*Mv)   // 65536

// Scratch for projected Q,K,V (layout: ((b*T+t)*M+m)*P + h*E + e)
__device__ float g_q[(size_t)ROWS * Pv];
__device__ float g_k[(size_t)ROWS * Pv];
__device__ float g_v[(size_t)ROWS * Pv];

__device__ __forceinline__ void split2(float x, half& hi, half& lo) {
    hi = __float2half_rn(x);
    lo = __float2half_rn(x - __half2float(hi));
}

// ===========================================================================
// QKV GEMM via wmma fp16 hi/lo split (3-term ~ fp32 accuracy).
// C[64x64] per block, A[65536x128] * W[128x256] + bias. 128 threads, 4 warps,
// each warp a 16x64 row strip.
// dyn smem: Ahi[64*136] Alo[64*136] Whi[128*72] Wlo[128*72]; Cs reuses Ahi.
// ===========================================================================
#define GA_LD 136
#define GW_LD 72
#define GC_LD 68
#define GEMM_SMEM ((64*GA_LD*2 + 128*GW_LD*2) * 2)   // 71680 bytes

__global__ void qkv_gemm_wmma(
    const float* __restrict__ A,
    const float* __restrict__ Wq, const float* __restrict__ bq,
    const float* __restrict__ Wk, const float* __restrict__ bk,
    const float* __restrict__ Wv, const float* __restrict__ bv)
{
    extern __shared__ char sm[];
    half*  Ahi = (half*)sm;
    half*  Alo = Ahi + 64 * GA_LD;
    half*  Whi = Alo + 64 * GA_LD;
    half*  Wlo = Whi + 128 * GW_LD;
    float* Cs  = (float*)sm;            // reuse Ahi region after mma

    const int which = blockIdx.z;
    const float* __restrict__ W    = (which == 0) ? Wq : (which == 1) ? Wk : Wv;
    const float* __restrict__ bias = (which == 0) ? bq : (which == 1) ? bk : bv;
    float* __restrict__ C          = (which == 0) ? g_q : (which == 1) ? g_k : g_v;

    const int tid = threadIdx.x;
    const int w   = tid >> 5;
    const int rowBase = blockIdx.x * 64;
    const int colBase = blockIdx.y * 64;

    // load + split A (64 x 128)
    for (int i = tid; i < 64 * 128; i += 128) {
        int r = i >> 7, k = i & 127;
        half hi, lo;
        split2(A[(size_t)(rowBase + r) * Dv + k], hi, lo);
        Ahi[r * GA_LD + k] = hi;
        Alo[r * GA_LD + k] = lo;
    }
    // load + split W (128 x 64)
    for (int i = tid; i < 128 * 64; i += 128) {
        int k = i >> 6, c = i & 63;
        half hi, lo;
        split2(W[(size_t)k * Pv + colBase + c], hi, lo);
        Whi[k * GW_LD + c] = hi;
        Wlo[k * GW_LD + c] = lo;
    }
    __syncthreads();

    wmma::fragment<wmma::accumulator, 16, 16, 16, float> c[4];
    #pragma unroll
    for (int n = 0; n < 4; n++) wmma::fill_fragment(c[n], 0.f);

    #pragma unroll
    for (int ks = 0; ks < 8; ks++) {
        wmma::fragment<wmma::matrix_a, 16, 16, 16, half, wmma::row_major> ah, al;
        wmma::load_matrix_sync(ah, &Ahi[w * 16 * GA_LD + ks * 16], GA_LD);
        wmma::load_matrix_sync(al, &Alo[w * 16 * GA_LD + ks * 16], GA_LD);
        #pragma unroll
        for (int n = 0; n < 4; n++) {
            wmma::fragment<wmma::matrix_b, 16, 16, 16, half, wmma::row_major> bh, bl;
            wmma::load_matrix_sync(bh, &Whi[ks * 16 * GW_LD + n * 16], GW_LD);
            wmma::load_matrix_sync(bl, &Wlo[ks * 16 * GW_LD + n * 16], GW_LD);
            wmma::mma_sync(c[n], ah, bh, c[n]);
            wmma::mma_sync(c[n], ah, bl, c[n]);
            wmma::mma_sync(c[n], al, bh, c[n]);
        }
    }
    // store to Cs (each warp writes only the A rows it alone was reading)
    #pragma unroll
    for (int n = 0; n < 4; n++)
        wmma::store_matrix_sync(&Cs[w * 16 * GC_LD + n * 16], c[n], GC_LD, wmma::mem_row_major);
    __syncthreads();

    for (int i = tid; i < 64 * 64; i += 128) {
        int r = i >> 6, cc = i & 63;
        C[(size_t)(rowBase + r) * Pv + colBase + cc] = Cs[r * GC_LD + cc] + bias[colBase + cc];
    }
}

// ===========================================================================
// Attention via wmma fp16 hi/lo split. One block = (bmh, 32-query tile),
// 256 threads (8 warps). Full T=512 score row in smem -> exact 2-pass softmax
// (no online rescale). P also hi/lo split; V hi/lo split.
// ===========================================================================
#define QT 32
#define KT 128
#define Q_LD 40
#define KV_LD 40
#define S_LD 512
#define P_LD 520
#define ATTN_SMEM (QT*Q_LD*2*2 + KT*KV_LD*2*2 + QT*S_LD*4 + Tv*4 + QT*4 + QT*P_LD*2*2) // 159872

__global__ __launch_bounds__(256) void attn_wmma(
    const int* __restrict__ mask, float* __restrict__ out)
{
    extern __shared__ char sm[];
    half*  Qhi  = (half*)sm;                 // 32 x 40
    half*  Qlo  = Qhi + QT * Q_LD;
    half*  KVhi = Qlo + QT * Q_LD;           // 128 x 40
    half*  KVlo = KVhi + KT * KV_LD;
    float* S    = (float*)(KVlo + KT * KV_LD);   // 32 x 512
    float* msk  = S + QT * S_LD;             // 512
    float* invl = msk + Tv;                  // 32
    half*  Phi  = (half*)(invl + QT);        // 32 x 520
    half*  Plo  = Phi + QT * P_LD;

    const int tid  = threadIdx.x;
    const int w    = tid >> 5;
    const int lane = tid & 31;
    const int qt   = blockIdx.x;             // 0..15
    const int bmh  = blockIdx.y;             // 0..1023
    const int h = bmh & (Hv - 1);
    const int m = (bmh >> 3) & (Mv - 1);
    const int b = bmh >> 7;
    const float scale = 0.17677669529663687f;   // 1/sqrt(32)

    // element offset for (b, t=0, m, h, e=0); row t adds t*4096 floats
    const size_t base = ((size_t)((size_t)b * Tv) * Mv + m) * Pv + (size_t)h * Ev;

    // ---- stage mask + Q (scale folded into Q before split) ----
    for (int i = tid; i < Tv; i += 256)
        msk[i] = mask[(size_t)(b * Tv + i) * Mv + m] ? 1.f : 0.f;
    for (int i = tid; i < QT * Ev; i += 256) {
        int r = i >> 5, e = i & 31;
        float q = g_q[base + (size_t)(qt * QT + r) * (Mv * Pv) + e] * scale;
        half hi, lo; split2(q, hi, lo);
        Qhi[r * Q_LD + e] = hi;
        Qlo[r * Q_LD + e] = lo;
    }

    // ---- phase 1: S = Qs @ K^T over 4 key tiles of 128 ----
    for (int kt = 0; kt < 4; kt++) {
        __syncthreads();
        for (int i = tid; i < KT * 8; i += 256) {
            int row = i >> 3, e4 = (i & 7) * 4;
            float4 kk = *(const float4*)&g_k[base + (size_t)(kt * KT + row) * (Mv * Pv) + e4];
            half h0, l0, h1, l1, h2, l2, h3, l3;
            split2(kk.x, h0, l0); split2(kk.y, h1, l1);
            split2(kk.z, h2, l2); split2(kk.w, h3, l3);
            KVhi[row * KV_LD + e4 + 0] = h0; KVlo[row * KV_LD + e4 + 0] = l0;
            KVhi[row * KV_LD + e4 + 1] = h1; KVlo[row * KV_LD + e4 + 1] = l1;
            KVhi[row * KV_LD + e4 + 2] = h2; KVlo[row * KV_LD + e4 + 2] = l2;
            KVhi[row * KV_LD + e4 + 3] = h3; KVlo[row * KV_LD + e4 + 3] = l3;
        }
        __syncthreads();

        // 16 tiles (2 row x 8 col) over 8 warps: warp w -> rt = w>>2, ct = (w&3)*2 + {0,1}
        const int rt = w >> 2;
        wmma::fragment<wmma::matrix_a, 16, 16, 16, half, wmma::row_major> ah0, al0, ah1, al1;
        wmma::load_matrix_sync(ah0, &Qhi[rt * 16 * Q_LD +  0], Q_LD);
        wmma::load_matrix_sync(al0, &Qlo[rt * 16 * Q_LD +  0], Q_LD);
        wmma::load_matrix_sync(ah1, &Qhi[rt * 16 * Q_LD + 16], Q_LD);
        wmma::load_matrix_sync(al1, &Qlo[rt * 16 * Q_LD + 16], Q_LD);
        #pragma unroll
        for (int cc = 0; cc < 2; cc++) {
            int ct = (w & 3) * 2 + cc;
            wmma::fragment<wmma::accumulator, 16, 16, 16, float> c;
            wmma::fill_fragment(c, 0.f);
            wmma::fragment<wmma::matrix_b, 16, 16, 16, half, wmma::col_major> bh, bl;
            // ks = 0
            wmma::load_matrix_sync(bh, &KVhi[ct * 16 * KV_LD + 0], KV_LD);
            wmma::load_matrix_sync(bl, &KVlo[ct * 16 * KV_LD + 0], KV_LD);
            wmma::mma_sync(c, ah0, bh, c);
            wmma::mma_sync(c, ah0, bl, c);
            wmma::mma_sync(c, al0, bh, c);
            // ks = 1
            wmma::load_matrix_sync(bh, &KVhi[ct * 16 * KV_LD + 16], KV_LD);
            wmma::load_matrix_sync(bl, &KVlo[ct * 16 * KV_LD + 16], KV_LD);
            wmma::mma_sync(c, ah1, bh, c);
            wmma::mma_sync(c, ah1, bl, c);
            wmma::mma_sync(c, al1, bh, c);
            wmma::store_matrix_sync(&S[rt * 16 * S_LD + kt * KT + ct * 16], c, S_LD, wmma::mem_row_major);
        }
    }
    __syncthreads();

    // ---- phase 2: exact softmax per row; store unnormalized p (hi/lo), 1/sum ----
    for (int rr = 0; rr < 4; rr++) {
        int r = w * 4 + rr;
        float mx = -1e30f;
        for (int cI = lane; cI < Tv; cI += 32) {
            float v = (msk[cI] != 0.f) ? S[r * S_LD + cI] : -1e30f;
            mx = fmaxf(mx, v);
        }
        #pragma unroll
        for (int o = 16; o > 0; o >>= 1) mx = fmaxf(mx, __shfl_xor_sync(0xffffffffu, mx, o));
        float sum = 0.f;
        for (int cI = lane; cI < Tv; cI += 32) {
            float p = (msk[cI] != 0.f) ? __expf(S[r * S_LD + cI] - mx) : 0.f;
            sum += p;
            half hi, lo; split2(p, hi, lo);
            Phi[r * P_LD + cI] = hi;
            Plo[r * P_LD + cI] = lo;
        }
        #pragma unroll
        for (int o = 16; o > 0; o >>= 1) sum += __shfl_xor_sync(0xffffffffu, sum, o);
        if (lane == 0) invl[r] = (sum > 0.f) ? 1.f / sum : 0.f;
    }
    __syncthreads();

    // ---- phase 3: O = P @ V. 4 O tiles (2x2 of 16x16) over 8 warps:
    // warp w -> tile (rt = (w>>1)&1, ce = w&1); k-range split by kh = w>>2
    // (group 0 does ks 0..3, group 1 ks 4..7 of every key tile).
    {
        wmma::fragment<wmma::accumulator, 16, 16, 16, float> oc;
        wmma::fill_fragment(oc, 0.f);
        const int rt = (w >> 1) & 1;
        const int ce = w & 1;
        const int kh = w >> 2;

        for (int kt = 0; kt < 4; kt++) {
            __syncthreads();
            for (int i = tid; i < KT * 8; i += 256) {
                int row = i >> 3, e4 = (i & 7) * 4;
                float4 vv = *(const float4*)&g_v[base + (size_t)(kt * KT + row) * (Mv * Pv) + e4];
                half h0, l0, h1, l1, h2, l2, h3, l3;
                split2(vv.x, h0, l0); split2(vv.y, h1, l1);
                split2(vv.z, h2, l2); split2(vv.w, h3, l3);
                KVhi[row * KV_LD + e4 + 0] = h0; KVlo[row * KV_LD + e4 + 0] = l0;
                KVhi[row * KV_LD + e4 + 1] = h1; KVlo[row * KV_LD + e4 + 1] = l1;
                KVhi[row * KV_LD + e4 + 2] = h2; KVlo[row * KV_LD + e4 + 2] = l2;
                KVhi[row * KV_LD + e4 + 3] = h3; KVlo[row * KV_LD + e4 + 3] = l3;
            }
            __syncthreads();

            #pragma unroll
            for (int ks2 = 0; ks2 < 4; ks2++) {
                int ks = kh * 4 + ks2;
                wmma::fragment<wmma::matrix_a, 16, 16, 16, half, wmma::row_major> ah, al;
                wmma::load_matrix_sync(ah, &Phi[rt * 16 * P_LD + kt * KT + ks * 16], P_LD);
                wmma::load_matrix_sync(al, &Plo[rt * 16 * P_LD + kt * KT + ks * 16], P_LD);
                wmma::fragment<wmma::matrix_b, 16, 16, 16, half, wmma::row_major> bh, bl;
                wmma::load_matrix_sync(bh, &KVhi[ks * 16 * KV_LD + ce * 16], KV_LD);
                wmma::load_matrix_sync(bl, &KVlo[ks * 16 * KV_LD + ce * 16], KV_LD);
                wmma::mma_sync(oc, ah, bh, oc);
                wmma::mma_sync(oc, ah, bl, oc);
                wmma::mma_sync(oc, al, bh, oc);
            }
        }
        __syncthreads();
        // stash the two k-half partials side by side in S, then combine
        wmma::store_matrix_sync(&S[rt * 16 * S_LD + kh * 64 + ce * 16], oc, S_LD, wmma::mem_row_major);
    }
    __syncthreads();

    for (int i = tid; i < QT * Ev; i += 256) {
        int r = i >> 5, e = i & 31;
        float val = (S[r * S_LD + e] + S[r * S_LD + 64 + e]) * invl[r];
        out[base + (size_t)(qt * QT + r) * (Mv * Pv) + e] = val;
    }
}

// ---------------------------------------------------------------------------
// Inputs (metadata order): inp, mask, Wq, bq, Wk, bk, Wv, bv
// ---------------------------------------------------------------------------
extern "C" void kernel_launch(void* const* d_in, const int* in_sizes, int n_in,
                              void* d_out, int out_size)
{
    (void)in_sizes; (void)n_in; (void)out_size;
    const float* inp  = (const float*)d_in[0];
    const int*   mask = (const int*)d_in[1];
    const float* Wq = (const float*)d_in[2];
    const float* bq = (const float*)d_in[3];
    const float* Wk = (const float*)d_in[4];
    const float* bk = (const float*)d_in[5];
    const float* Wv = (const float*)d_in[6];
    const float* bv = (const float*)d_in[7];
    float* out = (float*)d_out;

    cudaFuncSetAttribute(qkv_gemm_wmma, cudaFuncAttributeMaxDynamicSharedMemorySize, GEMM_SMEM);
    cudaFuncSetAttribute(attn_wmma,     cudaFuncAttributeMaxDynamicSharedMemorySize, ATTN_SMEM);

    dim3 ggrid(ROWS / 64, Pv / 64, 3);  // (1024, 4, 3)
    qkv_gemm_wmma<<<ggrid, 128, GEMM_SMEM>>>(inp, Wq, bq, Wk, bk, Wv, bv);

    dim3 agrid(Tv / QT, Bv * Mv * Hv);  // (16, 1024)
    attn_wmma<<<agrid, 256, ATTN_SMEM>>>(mask, out);
}

// round 7
// speedup vs baseline: 4.2787x; 4.2787x over previous
#include <cuda_runtime.h>
#include <cuda_fp16.h>
#include <cstdint>

#define Bv 8
#define Tv 512
#define Mv 16
#define Dv 128
#define Pv 256
#define Hv 8
#define Ev 32
#define ROWS (Bv*Tv*Mv)   // 65536
#define MP 4096           // Mv*Pv: element stride between consecutive t

// Scratch for projected Q,K,V (layout: ((b*T+t)*M+m)*P + h*E + e)
__device__ float g_q[(size_t)ROWS * Pv];
__device__ float g_k[(size_t)ROWS * Pv];
__device__ float g_v[(size_t)ROWS * Pv];

__device__ __forceinline__ void split2(float x, half& hi, half& lo) {
    hi = __float2half_rn(x);
    lo = __float2half_rn(x - __half2float(hi));
}
__device__ __forceinline__ void splitpack(float x, float y, uint32_t& hi, uint32_t& lo) {
    half hx, lx, hy, ly;
    split2(x, hx, lx);
    split2(y, hy, ly);
    __half2 h = __halves2half2(hx, hy);
    __half2 l = __halves2half2(lx, ly);
    hi = *(uint32_t*)&h;
    lo = *(uint32_t*)&l;
}
// D = A(16x16 f16, row) @ B(16x8 f16, col) + D (f32)
__device__ __forceinline__ void mma16816(float* c, const uint32_t* a, const uint32_t* b) {
    asm volatile(
        "mma.sync.aligned.m16n8k16.row.col.f32.f16.f16.f32 "
        "{%0,%1,%2,%3}, {%4,%5,%6,%7}, {%8,%9}, {%0,%1,%2,%3};\n"
        : "+f"(c[0]), "+f"(c[1]), "+f"(c[2]), "+f"(c[3])
        : "r"(a[0]), "r"(a[1]), "r"(a[2]), "r"(a[3]), "r"(b[0]), "r"(b[1]));
}

// ---------------------------------------------------------------------------
// Fused QKV projection (fp32 SIMT, at its FFMA roofline ~345us).
// ---------------------------------------------------------------------------
__global__ __launch_bounds__(256) void qkv_gemm(
    const float* __restrict__ A,
    const float* __restrict__ Wq, const float* __restrict__ bq,
    const float* __restrict__ Wk, const float* __restrict__ bk,
    const float* __restrict__ Wv, const float* __restrict__ bv)
{
    __shared__ float As[64][65];
    __shared__ float Bs[64][64];

    const int which = blockIdx.z;
    const float* __restrict__ W    = (which == 0) ? Wq : (which == 1) ? Wk : Wv;
    const float* __restrict__ bias = (which == 0) ? bq : (which == 1) ? bk : bv;
    float* __restrict__ C          = (which == 0) ? g_q : (which == 1) ? g_k : g_v;

    const int tid = threadIdx.x;
    const int tx  = tid & 15;
    const int ty  = tid >> 4;
    const int rowBase = blockIdx.x * 64;
    const int colBase = blockIdx.y * 64;

    float acc[4][4] = {};

    for (int kk = 0; kk < Dv; kk += 64) {
        #pragma unroll
        for (int i = tid; i < 64 * 64; i += 256) {
            int r = i >> 6, k = i & 63;
            As[r][k] = A[(size_t)(rowBase + r) * Dv + kk + k];
        }
        #pragma unroll
        for (int i = tid; i < 64 * 64; i += 256) {
            int k = i >> 6, c = i & 63;
            Bs[k][c] = W[(size_t)(kk + k) * Pv + colBase + c];
        }
        __syncthreads();

        #pragma unroll 16
        for (int k = 0; k < 64; k++) {
            float a0 = As[ty * 4 + 0][k];
            float a1 = As[ty * 4 + 1][k];
            float a2 = As[ty * 4 + 2][k];
            float a3 = As[ty * 4 + 3][k];
            float4 bb = *(const float4*)&Bs[k][tx * 4];
            acc[0][0] += a0 * bb.x; acc[0][1] += a0 * bb.y; acc[0][2] += a0 * bb.z; acc[0][3] += a0 * bb.w;
            acc[1][0] += a1 * bb.x; acc[1][1] += a1 * bb.y; acc[1][2] += a1 * bb.z; acc[1][3] += a1 * bb.w;
            acc[2][0] += a2 * bb.x; acc[2][1] += a2 * bb.y; acc[2][2] += a2 * bb.z; acc[2][3] += a2 * bb.w;
            acc[3][0] += a3 * bb.x; acc[3][1] += a3 * bb.y; acc[3][2] += a3 * bb.z; acc[3][3] += a3 * bb.w;
        }
        __syncthreads();
    }

    #pragma unroll
    for (int i = 0; i < 4; i++) {
        int r = rowBase + ty * 4 + i;
        float4 o;
        o.x = acc[i][0] + bias[colBase + tx * 4 + 0];
        o.y = acc[i][1] + bias[colBase + tx * 4 + 1];
        o.z = acc[i][2] + bias[colBase + tx * 4 + 2];
        o.w = acc[i][3] + bias[colBase + tx * 4 + 3];
        *(float4*)&C[(size_t)r * Pv + colBase + tx * 4] = o;
    }
}

// ---------------------------------------------------------------------------
// Flash attention with PTX mma.m16n8k16, fp16 hi/lo 3-term splits.
// Block = (128-query tile, bmh), 8 warps; warp owns 16 q rows.
// Loop over 8 key tiles of 64; online softmax entirely in registers
// (m16n8 C-fragment layout: rows g=lane/4, g+8; cols (lane&3)*2+{0,1}).
// ---------------------------------------------------------------------------
__global__ __launch_bounds__(256) void attn_mma(
    const int* __restrict__ mask, float* __restrict__ out)
{
    __shared__ half Khi[64][40];   // [key][e], stride 40 halfs: conflict-free B-frag reads
    __shared__ half Klo[64][40];
    __shared__ half Vthi[32][72];  // [e][key], stride 72: conflict-free B-frag reads
    __shared__ half Vtlo[32][72];
    __shared__ float msk[64];

    const int tid  = threadIdx.x;
    const int w    = tid >> 5;
    const int lane = tid & 31;
    const int g    = lane >> 2;         // 0..7
    const int c2   = (lane & 3) * 2;    // 0,2,4,6
    const int qt   = blockIdx.x;        // 0..3
    const int bmh  = blockIdx.y;        // 0..1023
    const int h  = bmh & (Hv - 1);
    const int m_ = (bmh >> 3) & (Mv - 1);
    const int b  = bmh >> 7;
    const float scale = 0.17677669529663687f;   // 1/sqrt(32)

    const size_t base = ((size_t)b * Tv * Mv + m_) * (size_t)Pv + (size_t)h * Ev;
    const int qrow = qt * 128 + w * 16 + g;     // thread's first q row; second is +8

    // ---- Q fragments (scale folded), A-frag layout for m16n8k16 ----
    uint32_t qh[2][4], ql[2][4];
    {
        const float* q0 = &g_q[base + (size_t)qrow * MP];
        const float* q1 = q0 + (size_t)8 * MP;
        #pragma unroll
        for (int ks = 0; ks < 2; ks++) {
            int c = ks * 16 + c2;
            splitpack(q0[c] * scale,     q0[c + 1] * scale, qh[ks][0], ql[ks][0]);
            splitpack(q1[c] * scale,     q1[c + 1] * scale, qh[ks][1], ql[ks][1]);
            splitpack(q0[c + 8] * scale, q0[c + 9] * scale, qh[ks][2], ql[ks][2]);
            splitpack(q1[c + 8] * scale, q1[c + 9] * scale, qh[ks][3], ql[ks][3]);
        }
    }

    float O[4][4] = {};
    float mrow0 = -1e30f, mrow1 = -1e30f;
    float lrow0 = 0.f,    lrow1 = 0.f;

    for (int kt = 0; kt < 8; kt++) {
        __syncthreads();
        for (int i = tid; i < 64 * 32; i += 256) {
            int row = i >> 5, e = i & 31;
            size_t off = base + (size_t)(kt * 64 + row) * MP + e;
            half hh, hl;
            split2(g_k[off], hh, hl);
            Khi[row][e] = hh;  Klo[row][e] = hl;
            split2(g_v[off], hh, hl);
            Vthi[e][row] = hh; Vtlo[e][row] = hl;
        }
        if (tid < 64)
            msk[tid] = mask[(size_t)(b * Tv + kt * 64 + tid) * Mv + m_] ? 1.f : 0.f;
        __syncthreads();

        // ---- S = Qs @ K^T : 8 nblocks of 8 keys, 2 ksteps, 3 split terms ----
        float S[8][4];
        #pragma unroll
        for (int nb = 0; nb < 8; nb++) {
            S[nb][0] = S[nb][1] = S[nb][2] = S[nb][3] = 0.f;
            #pragma unroll
            for (int ks = 0; ks < 2; ks++) {
                uint32_t bh[2], bl[2];
                const half* kp = &Khi[nb * 8 + g][ks * 16 + c2];
                bh[0] = *(const uint32_t*)kp;  bh[1] = *(const uint32_t*)(kp + 8);
                const half* lp = &Klo[nb * 8 + g][ks * 16 + c2];
                bl[0] = *(const uint32_t*)lp;  bl[1] = *(const uint32_t*)(lp + 8);
                mma16816(S[nb], qh[ks], bh);
                mma16816(S[nb], qh[ks], bl);
                mma16816(S[nb], ql[ks], bh);
            }
        }

        // ---- mask + row max (C-frag cols = nb*8 + c2 + {0,1}) ----
        float mt0 = -1e30f, mt1 = -1e30f;
        #pragma unroll
        for (int nb = 0; nb < 8; nb++) {
            float mk0 = msk[nb * 8 + c2];
            float mk1 = msk[nb * 8 + c2 + 1];
            S[nb][0] = (mk0 != 0.f) ? S[nb][0] : -1e30f;
            S[nb][1] = (mk1 != 0.f) ? S[nb][1] : -1e30f;
            S[nb][2] = (mk0 != 0.f) ? S[nb][2] : -1e30f;
            S[nb][3] = (mk1 != 0.f) ? S[nb][3] : -1e30f;
            mt0 = fmaxf(mt0, fmaxf(S[nb][0], S[nb][1]));
            mt1 = fmaxf(mt1, fmaxf(S[nb][2], S[nb][3]));
        }
        mt0 = fmaxf(mt0, __shfl_xor_sync(0xffffffffu, mt0, 1));
        mt0 = fmaxf(mt0, __shfl_xor_sync(0xffffffffu, mt0, 2));
        mt1 = fmaxf(mt1, __shfl_xor_sync(0xffffffffu, mt1, 1));
        mt1 = fmaxf(mt1, __shfl_xor_sync(0xffffffffu, mt1, 2));

        float mn0 = fmaxf(mrow0, mt0), mn1 = fmaxf(mrow1, mt1);
        float a0 = __expf(mrow0 - mn0), a1 = __expf(mrow1 - mn1);
        mrow0 = mn0; mrow1 = mn1;

        float rs0 = 0.f, rs1 = 0.f;
        #pragma unroll
        for (int nb = 0; nb < 8; nb++) {
            S[nb][0] = __expf(S[nb][0] - mn0);
            S[nb][1] = __expf(S[nb][1] - mn0);
            S[nb][2] = __expf(S[nb][2] - mn1);
            S[nb][3] = __expf(S[nb][3] - mn1);
            rs0 += S[nb][0] + S[nb][1];
            rs1 += S[nb][2] + S[nb][3];
        }
        rs0 += __shfl_xor_sync(0xffffffffu, rs0, 1);
        rs0 += __shfl_xor_sync(0xffffffffu, rs0, 2);
        rs1 += __shfl_xor_sync(0xffffffffu, rs1, 1);
        rs1 += __shfl_xor_sync(0xffffffffu, rs1, 2);
        lrow0 = lrow0 * a0 + rs0;
        lrow1 = lrow1 * a1 + rs1;
        #pragma unroll
        for (int eb = 0; eb < 4; eb++) {
            O[eb][0] *= a0; O[eb][1] *= a0;
            O[eb][2] *= a1; O[eb][3] *= a1;
        }

        // ---- O += P @ V : P A-frags come straight from S C-frags ----
        #pragma unroll
        for (int kb = 0; kb < 4; kb++) {
            uint32_t ph[4], pl[4];
            splitpack(S[2 * kb][0],     S[2 * kb][1],     ph[0], pl[0]);
            splitpack(S[2 * kb][2],     S[2 * kb][3],     ph[1], pl[1]);
            splitpack(S[2 * kb + 1][0], S[2 * kb + 1][1], ph[2], pl[2]);
            splitpack(S[2 * kb + 1][2], S[2 * kb + 1][3], ph[3], pl[3]);
            #pragma unroll
            for (int eb = 0; eb < 4; eb++) {
                uint32_t vh[2], vl[2];
                const half* vp = &Vthi[eb * 8 + g][kb * 16 + c2];
                vh[0] = *(const uint32_t*)vp;  vh[1] = *(const uint32_t*)(vp + 8);
                const half* vq = &Vtlo[eb * 8 + g][kb * 16 + c2];
                vl[0] = *(const uint32_t*)vq;  vl[1] = *(const uint32_t*)(vq + 8);
                mma16816(O[eb], ph, vh);
                mma16816(O[eb], ph, vl);
                mma16816(O[eb], pl, vh);
            }
        }
    }

    // all-masked row -> m never rose above -1e30 -> output 0 (matches reference)
    float inv0 = (mrow0 > -1e29f) ? (1.f / lrow0) : 0.f;
    float inv1 = (mrow1 > -1e29f) ? (1.f / lrow1) : 0.f;
    float* o0 = &out[base + (size_t)qrow * MP];
    float* o1 = o0 + (size_t)8 * MP;
    #pragma unroll
    for (int eb = 0; eb < 4; eb++) {
        int e = eb * 8 + c2;
        o0[e]     = O[eb][0] * inv0;
        o0[e + 1] = O[eb][1] * inv0;
        o1[e]     = O[eb][2] * inv1;
        o1[e + 1] = O[eb][3] * inv1;
    }
}

// ---------------------------------------------------------------------------
// Inputs (metadata order): inp, mask, Wq, bq, Wk, bk, Wv, bv
// ---------------------------------------------------------------------------
extern "C" void kernel_launch(void* const* d_in, const int* in_sizes, int n_in,
                              void* d_out, int out_size)
{
    (void)in_sizes; (void)n_in; (void)out_size;
    const float* inp  = (const float*)d_in[0];
    const int*   mask = (const int*)d_in[1];
    const float* Wq = (const float*)d_in[2];
    const float* bq = (const float*)d_in[3];
    const float* Wk = (const float*)d_in[4];
    const float* bk = (const float*)d_in[5];
    const float* Wv = (const float*)d_in[6];
    const float* bv = (const float*)d_in[7];
    float* out = (float*)d_out;

    dim3 ggrid(ROWS / 64, Pv / 64, 3);  // (1024, 4, 3)
    qkv_gemm<<<ggrid, 256>>>(inp, Wq, bq, Wk, bk, Wv, bv);

    dim3 agrid(Tv / 128, Bv * Mv * Hv); // (4, 1024)
    attn_mma<<<agrid, 256>>>(mask, out);
}

// round 8
// speedup vs baseline: 5.0661x; 1.1840x over previous
#include <cuda_runtime.h>
#include <cuda_fp16.h>
#include <cstdint>

#define Bv 8
#define Tv 512
#define Mv 16
#define Dv 128
#define Pv 256
#define Hv 8
#define Ev 32
#define ROWS (Bv*Tv*Mv)   // 65536
#define MP 4096           // Mv*Pv: element stride between consecutive t

// Scratch for projected Q,K,V (layout: ((b*T+t)*M+m)*P + h*E + e)
__device__ float g_q[(size_t)ROWS * Pv];
__device__ float g_k[(size_t)ROWS * Pv];
__device__ float g_v[(size_t)ROWS * Pv];

__device__ __forceinline__ void split2(float x, half& hi, half& lo) {
    hi = __float2half_rn(x);
    lo = __float2half_rn(x - __half2float(hi));
}
__device__ __forceinline__ void splitpack(float x, float y, uint32_t& hi, uint32_t& lo) {
    half hx, lx, hy, ly;
    split2(x, hx, lx);
    split2(y, hy, ly);
    __half2 h = __halves2half2(hx, hy);
    __half2 l = __halves2half2(lx, ly);
    hi = *(uint32_t*)&h;
    lo = *(uint32_t*)&l;
}
// D = A(16x16 f16, row) @ B(16x8 f16, col) + D (f32)
__device__ __forceinline__ void mma16816(float* c, const uint32_t* a, const uint32_t* b) {
    asm volatile(
        "mma.sync.aligned.m16n8k16.row.col.f32.f16.f16.f32 "
        "{%0,%1,%2,%3}, {%4,%5,%6,%7}, {%8,%9}, {%0,%1,%2,%3};\n"
        : "+f"(c[0]), "+f"(c[1]), "+f"(c[2]), "+f"(c[3])
        : "r"(a[0]), "r"(a[1]), "r"(a[2]), "r"(a[3]), "r"(b[0]), "r"(b[1]));
}

// ===========================================================================
// QKV GEMM via mma.m16n8k16 with fp16 hi/lo 3-term splits.
// Block: 128x128 output tile, 256 threads (8 warps; warp = 16 rows x 128 cols).
// BK = 64: A tile [128][64] hi/lo, W tile transposed [128 cols][64 k] hi/lo.
// Grid: (512, 2, 3).
// ===========================================================================
#define GLD 72                                    // smem leading dim (halfs)
#define GEMM_SMEM (4 * 128 * GLD * 2)             // 73728 bytes

__global__ __launch_bounds__(256) void qkv_gemm_mma(
    const float* __restrict__ A,
    const float* __restrict__ Wq, const float* __restrict__ bq,
    const float* __restrict__ Wk, const float* __restrict__ bk,
    const float* __restrict__ Wv, const float* __restrict__ bv)
{
    extern __shared__ half sm[];
    half* Ahi = sm;                 // [128][GLD]
    half* Alo = Ahi + 128 * GLD;
    half* Bhi = Alo + 128 * GLD;    // [c][k]  (col-major for B-frag)
    half* Blo = Bhi + 128 * GLD;

    const int which = blockIdx.z;
    const float* __restrict__ W    = (which == 0) ? Wq : (which == 1) ? Wk : Wv;
    const float* __restrict__ bias = (which == 0) ? bq : (which == 1) ? bk : bv;
    float* __restrict__ C          = (which == 0) ? g_q : (which == 1) ? g_k : g_v;

    const int tid  = threadIdx.x;
    const int w    = tid >> 5;
    const int lane = tid & 31;
    const int g    = lane >> 2;          // 0..7
    const int c2   = (lane & 3) * 2;     // 0,2,4,6
    const int rowBase = blockIdx.x * 128;
    const int colBase = blockIdx.y * 128;

    float acc[16][4];
    #pragma unroll
    for (int nb = 0; nb < 16; nb++)
        acc[nb][0] = acc[nb][1] = acc[nb][2] = acc[nb][3] = 0.f;

    for (int kk = 0; kk < Dv; kk += 64) {
        __syncthreads();
        // A tile: 128 rows x 64 k as float4 (coalesced); split + pack to smem
        for (int i = tid; i < 128 * 16; i += 256) {
            int r = i >> 4, k4 = (i & 15) * 4;
            float4 a = *(const float4*)&A[(size_t)(rowBase + r) * Dv + kk + k4];
            uint32_t h0, l0, h1, l1;
            splitpack(a.x, a.y, h0, l0);
            splitpack(a.z, a.w, h1, l1);
            *(uint32_t*)&Ahi[r * GLD + k4]     = h0;
            *(uint32_t*)&Ahi[r * GLD + k4 + 2] = h1;
            *(uint32_t*)&Alo[r * GLD + k4]     = l0;
            *(uint32_t*)&Alo[r * GLD + k4 + 2] = l1;
        }
        // W tile: thread owns (c, k4..k4+3); 4 coalesced scalar loads (W is
        // tiny + L2 resident), write transposed [c][k] contiguous in k.
        for (int i = tid; i < 128 * 16; i += 256) {
            int c = i >> 4, k4 = (i & 15) * 4;
            float w0 = W[(size_t)(kk + k4 + 0) * Pv + colBase + c];
            float w1 = W[(size_t)(kk + k4 + 1) * Pv + colBase + c];
            float w2 = W[(size_t)(kk + k4 + 2) * Pv + colBase + c];
            float w3 = W[(size_t)(kk + k4 + 3) * Pv + colBase + c];
            uint32_t h0, l0, h1, l1;
            splitpack(w0, w1, h0, l0);
            splitpack(w2, w3, h1, l1);
            *(uint32_t*)&Bhi[c * GLD + k4]     = h0;
            *(uint32_t*)&Bhi[c * GLD + k4 + 2] = h1;
            *(uint32_t*)&Blo[c * GLD + k4]     = l0;
            *(uint32_t*)&Blo[c * GLD + k4 + 2] = l1;
        }
        __syncthreads();

        #pragma unroll
        for (int ks = 0; ks < 4; ks++) {
            uint32_t ah[4], al[4];
            const half* a0 = &Ahi[(w * 16 + g) * GLD + ks * 16 + c2];
            const half* a1 = a0 + 8 * GLD;
            ah[0] = *(const uint32_t*)a0;
            ah[1] = *(const uint32_t*)a1;
            ah[2] = *(const uint32_t*)(a0 + 8);
            ah[3] = *(const uint32_t*)(a1 + 8);
            const half* b0 = &Alo[(w * 16 + g) * GLD + ks * 16 + c2];
            const half* b1 = b0 + 8 * GLD;
            al[0] = *(const uint32_t*)b0;
            al[1] = *(const uint32_t*)b1;
            al[2] = *(const uint32_t*)(b0 + 8);
            al[3] = *(const uint32_t*)(b1 + 8);

            #pragma unroll
            for (int nb = 0; nb < 16; nb++) {
                uint32_t bh[2], bl[2];
                const half* bp = &Bhi[(nb * 8 + g) * GLD + ks * 16 + c2];
                bh[0] = *(const uint32_t*)bp;
                bh[1] = *(const uint32_t*)(bp + 8);
                const half* lp = &Blo[(nb * 8 + g) * GLD + ks * 16 + c2];
                bl[0] = *(const uint32_t*)lp;
                bl[1] = *(const uint32_t*)(lp + 8);
                mma16816(acc[nb], ah, bh);
                mma16816(acc[nb], ah, bl);
                mma16816(acc[nb], al, bh);
            }
        }
    }

    const int r0 = rowBase + w * 16 + g;
    const int r1 = r0 + 8;
    #pragma unroll
    for (int nb = 0; nb < 16; nb++) {
        int col = colBase + nb * 8 + c2;
        float bx = __ldg(&bias[col]);
        float by = __ldg(&bias[col + 1]);
        float2 v0 = make_float2(acc[nb][0] + bx, acc[nb][1] + by);
        float2 v1 = make_float2(acc[nb][2] + bx, acc[nb][3] + by);
        *(float2*)&C[(size_t)r0 * Pv + col] = v0;
        *(float2*)&C[(size_t)r1 * Pv + col] = v1;
    }
}

// ---------------------------------------------------------------------------
// Flash attention with PTX mma.m16n8k16, fp16 hi/lo 3-term splits (unchanged).
// ---------------------------------------------------------------------------
__global__ __launch_bounds__(256) void attn_mma(
    const int* __restrict__ mask, float* __restrict__ out)
{
    __shared__ half Khi[64][40];
    __shared__ half Klo[64][40];
    __shared__ half Vthi[32][72];
    __shared__ half Vtlo[32][72];
    __shared__ float msk[64];

    const int tid  = threadIdx.x;
    const int w    = tid >> 5;
    const int lane = tid & 31;
    const int g    = lane >> 2;
    const int c2   = (lane & 3) * 2;
    const int qt   = blockIdx.x;
    const int bmh  = blockIdx.y;
    const int h  = bmh & (Hv - 1);
    const int m_ = (bmh >> 3) & (Mv - 1);
    const int b  = bmh >> 7;
    const float scale = 0.17677669529663687f;

    const size_t base = ((size_t)b * Tv * Mv + m_) * (size_t)Pv + (size_t)h * Ev;
    const int qrow = qt * 128 + w * 16 + g;

    uint32_t qh[2][4], ql[2][4];
    {
        const float* q0 = &g_q[base + (size_t)qrow * MP];
        const float* q1 = q0 + (size_t)8 * MP;
        #pragma unroll
        for (int ks = 0; ks < 2; ks++) {
            int c = ks * 16 + c2;
            splitpack(q0[c] * scale,     q0[c + 1] * scale, qh[ks][0], ql[ks][0]);
            splitpack(q1[c] * scale,     q1[c + 1] * scale, qh[ks][1], ql[ks][1]);
            splitpack(q0[c + 8] * scale, q0[c + 9] * scale, qh[ks][2], ql[ks][2]);
            splitpack(q1[c + 8] * scale, q1[c + 9] * scale, qh[ks][3], ql[ks][3]);
        }
    }

    float O[4][4] = {};
    float mrow0 = -1e30f, mrow1 = -1e30f;
    float lrow0 = 0.f,    lrow1 = 0.f;

    for (int kt = 0; kt < 8; kt++) {
        __syncthreads();
        for (int i = tid; i < 64 * 32; i += 256) {
            int row = i >> 5, e = i & 31;
            size_t off = base + (size_t)(kt * 64 + row) * MP + e;
            half hh, hl;
            split2(g_k[off], hh, hl);
            Khi[row][e] = hh;  Klo[row][e] = hl;
            split2(g_v[off], hh, hl);
            Vthi[e][row] = hh; Vtlo[e][row] = hl;
        }
        if (tid < 64)
            msk[tid] = mask[(size_t)(b * Tv + kt * 64 + tid) * Mv + m_] ? 1.f : 0.f;
        __syncthreads();

        float S[8][4];
        #pragma unroll
        for (int nb = 0; nb < 8; nb++) {
            S[nb][0] = S[nb][1] = S[nb][2] = S[nb][3] = 0.f;
            #pragma unroll
            for (int ks = 0; ks < 2; ks++) {
                uint32_t bh[2], bl[2];
                const half* kp = &Khi[nb * 8 + g][ks * 16 + c2];
                bh[0] = *(const uint32_t*)kp;  bh[1] = *(const uint32_t*)(kp + 8);
                const half* lp = &Klo[nb * 8 + g][ks * 16 + c2];
                bl[0] = *(const uint32_t*)lp;  bl[1] = *(const uint32_t*)(lp + 8);
                mma16816(S[nb], qh[ks], bh);
                mma16816(S[nb], qh[ks], bl);
                mma16816(S[nb], ql[ks], bh);
            }
        }

        float mt0 = -1e30f, mt1 = -1e30f;
        #pragma unroll
        for (int nb = 0; nb < 8; nb++) {
            float mk0 = msk[nb * 8 + c2];
            float mk1 = msk[nb * 8 + c2 + 1];
            S[nb][0] = (mk0 != 0.f) ? S[nb][0] : -1e30f;
            S[nb][1] = (mk1 != 0.f) ? S[nb][1] : -1e30f;
            S[nb][2] = (mk0 != 0.f) ? S[nb][2] : -1e30f;
            S[nb][3] = (mk1 != 0.f) ? S[nb][3] : -1e30f;
            mt0 = fmaxf(mt0, fmaxf(S[nb][0], S[nb][1]));
            mt1 = fmaxf(mt1, fmaxf(S[nb][2], S[nb][3]));
        }
        mt0 = fmaxf(mt0, __shfl_xor_sync(0xffffffffu, mt0, 1));
        mt0 = fmaxf(mt0, __shfl_xor_sync(0xffffffffu, mt0, 2));
        mt1 = fmaxf(mt1, __shfl_xor_sync(0xffffffffu, mt1, 1));
        mt1 = fmaxf(mt1, __shfl_xor_sync(0xffffffffu, mt1, 2));

        float mn0 = fmaxf(mrow0, mt0), mn1 = fmaxf(mrow1, mt1);
        float a0 = __expf(mrow0 - mn0), a1 = __expf(mrow1 - mn1);
        mrow0 = mn0; mrow1 = mn1;

        float rs0 = 0.f, rs1 = 0.f;
        #pragma unroll
        for (int nb = 0; nb < 8; nb++) {
            S[nb][0] = __expf(S[nb][0] - mn0);
            S[nb][1] = __expf(S[nb][1] - mn0);
            S[nb][2] = __expf(S[nb][2] - mn1);
            S[nb][3] = __expf(S[nb][3] - mn1);
            rs0 += S[nb][0] + S[nb][1];
            rs1 += S[nb][2] + S[nb][3];
        }
        rs0 += __shfl_xor_sync(0xffffffffu, rs0, 1);
        rs0 += __shfl_xor_sync(0xffffffffu, rs0, 2);
        rs1 += __shfl_xor_sync(0xffffffffu, rs1, 1);
        rs1 += __shfl_xor_sync(0xffffffffu, rs1, 2);
        lrow0 = lrow0 * a0 + rs0;
        lrow1 = lrow1 * a1 + rs1;
        #pragma unroll
        for (int eb = 0; eb < 4; eb++) {
            O[eb][0] *= a0; O[eb][1] *= a0;
            O[eb][2] *= a1; O[eb][3] *= a1;
        }

        #pragma unroll
        for (int kb = 0; kb < 4; kb++) {
            uint32_t ph[4], pl[4];
            splitpack(S[2 * kb][0],     S[2 * kb][1],     ph[0], pl[0]);
            splitpack(S[2 * kb][2],     S[2 * kb][3],     ph[1], pl[1]);
            splitpack(S[2 * kb + 1][0], S[2 * kb + 1][1], ph[2], pl[2]);
            splitpack(S[2 * kb + 1][2], S[2 * kb + 1][3], ph[3], pl[3]);
            #pragma unroll
            for (int eb = 0; eb < 4; eb++) {
                uint32_t vh[2], vl[2];
                const half* vp = &Vthi[eb * 8 + g][kb * 16 + c2];
                vh[0] = *(const uint32_t*)vp;  vh[1] = *(const uint32_t*)(vp + 8);
                const half* vq = &Vtlo[eb * 8 + g][kb * 16 + c2];
                vl[0] = *(const uint32_t*)vq;  vl[1] = *(const uint32_t*)(vq + 8);
                mma16816(O[eb], ph, vh);
                mma16816(O[eb], ph, vl);
                mma16816(O[eb], pl, vh);
            }
        }
    }

    float inv0 = (mrow0 > -1e29f) ? (1.f / lrow0) : 0.f;
    float inv1 = (mrow1 > -1e29f) ? (1.f / lrow1) : 0.f;
    float* o0 = &out[base + (size_t)qrow * MP];
    float* o1 = o0 + (size_t)8 * MP;
    #pragma unroll
    for (int eb = 0; eb < 4; eb++) {
        int e = eb * 8 + c2;
        o0[e]     = O[eb][0] * inv0;
        o0[e + 1] = O[eb][1] * inv0;
        o1[e]     = O[eb][2] * inv1;
        o1[e + 1] = O[eb][3] * inv1;
    }
}

// ---------------------------------------------------------------------------
// Inputs (metadata order): inp, mask, Wq, bq, Wk, bk, Wv, bv
// ---------------------------------------------------------------------------
extern "C" void kernel_launch(void* const* d_in, const int* in_sizes, int n_in,
                              void* d_out, int out_size)
{
    (void)in_sizes; (void)n_in; (void)out_size;
    const float* inp  = (const float*)d_in[0];
    const int*   mask = (const int*)d_in[1];
    const float* Wq = (const float*)d_in[2];
    const float* bq = (const float*)d_in[3];
    const float* Wk = (const float*)d_in[4];
    const float* bk = (const float*)d_in[5];
    const float* Wv = (const float*)d_in[6];
    const float* bv = (const float*)d_in[7];
    float* out = (float*)d_out;

    static bool attr_done = false;
    if (!attr_done) {
        cudaFuncSetAttribute(qkv_gemm_mma, cudaFuncAttributeMaxDynamicSharedMemorySize, GEMM_SMEM);
        attr_done = true;
    }

    dim3 ggrid(ROWS / 128, Pv / 128, 3);   // (512, 2, 3)
    qkv_gemm_mma<<<ggrid, 256, GEMM_SMEM>>>(inp, Wq, bq, Wk, bk, Wv, bv);

    dim3 agrid(Tv / 128, Bv * Mv * Hv);    // (4, 1024)
    attn_mma<<<agrid, 256>>>(mask, out);
}